// round 12
// baseline (speedup 1.0000x reference)
#include <cuda_runtime.h>
#include <cuda_bf16.h>
#include <cstdint>

#define N_NODES 50000
#define N_EDGES 800000
#define LATDIM  128
#define PAD     18          // ull stride per row/col in smem (bank-conflict-free)

typedef unsigned long long ull;

// ---- scratch (static device globals: the sanctioned no-alloc workaround) ----
__device__ float g_Q[N_NODES * LATDIM];
__device__ float g_K[N_NODES * LATDIM];
__device__ float g_V[N_NODES * LATDIM];
__device__ int   g_cnt[N_NODES];       // zero-init; re-zeroed by scan each run
__device__ int   g_bsum[64];           // lookback slots: 0 = unpublished, else total+1
__device__ int   g_rowptr[N_NODES + 1];
__device__ int   g_fill[N_NODES];
__device__ int   g_adj[N_EDGES];

// ---- packed f32x2 helpers (base sm_103 PTX — no 'a' features) ----
__device__ __forceinline__ ull pack2(float lo, float hi) {
    ull r;
    asm("mov.b64 %0, {%1, %2};" : "=l"(r)
        : "r"(__float_as_uint(lo)), "r"(__float_as_uint(hi)));
    return r;
}
__device__ __forceinline__ void fma2(ull& d, ull a, ull b) {
    asm("fma.rn.f32x2 %0, %1, %2, %3;" : "=l"(d) : "l"(a), "l"(b), "l"(d));
}
__device__ __forceinline__ void unpack2(ull v, float& lo, float& hi) {
    unsigned ulo, uhi;
    asm("mov.b64 {%0, %1}, %2;" : "=r"(ulo), "=r"(uhi) : "l"(v));
    lo = __uint_as_float(ulo);
    hi = __uint_as_float(uhi);
}
__device__ __forceinline__ uint32_t smem_u32(const void* p) {
    uint32_t a;
    asm("{ .reg .u64 t; cvta.to.shared.u64 t, %1; cvt.u32.u64 %0, t; }"
        : "=r"(a) : "l"(p));
    return a;
}
#define CP_ASYNC16(dst_u32, src) \
    asm volatile("cp.async.ca.shared.global [%0], [%1], 16;" \
                 :: "r"(dst_u32), "l"(src) : "memory")
#define CP_COMMIT() asm volatile("cp.async.commit_group;" ::: "memory")
#define CP_WAIT1()  asm volatile("cp.async.wait_group 1;" ::: "memory")
#define CP_WAIT0()  asm volatile("cp.async.wait_group 0;" ::: "memory")

// ============================================================
// Kernel 1: fused Q/K/V projection + edge histogram.
// grid = (ceil(N/128), 4): y<3 GEMM slices, y==3 histogram.
//
// k-pair FFMA2 scheme: acc{r,c} accumulates {even-k, odd-k} partial
// sums in the two f32x2 lanes; output = lo + hi. Both operands are
// natural memory pairs -> ZERO pack MOVs in the mainloop (vs 16/k
// before). A tile = raw global bytes (cp.async, double-buffered);
// B tile k-pair packed at load (8 pack MOVs per chunk per thread).
// Mainloop per 4k: 64 FFMA2 + 12 LDS.128 -> ~80% fma issue fraction.
// ============================================================
__global__ __launch_bounds__(512, 1)
void gemm3_hist_kernel(const float* __restrict__ E,
                       const float* __restrict__ qW,
                       const float* __restrict__ kW,
                       const float* __restrict__ vW,
                       const int* __restrict__ rows,
                       int N, int nE)
{
    // --- histogram slice: scheduled after GEMM blocks, fills the tail wave ---
    if (blockIdx.y == 3) {
        int stride = gridDim.x * blockDim.x;
        for (int e = blockIdx.x * blockDim.x + threadIdx.x; e < nE; e += stride)
            atomicAdd(&g_cnt[rows[e]], 1);
        return;
    }

    __shared__ ull Asp[2][128 * PAD];   // [buf][row*PAD + kp]   2 x 18KB
    __shared__ ull Bsp[2][128 * PAD];   // [buf][col*PAD + kp]   2 x 18KB

    const float* W   = (blockIdx.y == 0) ? qW : (blockIdx.y == 1 ? kW : vW);
    float*       Out = (blockIdx.y == 0) ? g_Q : (blockIdx.y == 1 ? g_K : g_V);

    const int row0 = blockIdx.x * 128;
    const int tid  = threadIdx.x;
    const int tidc = tid & 31;          // cols: tidc + {0,32,64,96}
    const int tidr = tid >> 5;          // rows: tidr*8 .. +8

    // A-load mapping: 2 float4 (=4 ull kp) per thread
    const int ar = tid >> 2;            // row 0..127
    const int aq = tid & 3;             // kp quad 0..3 (k offset aq*8)
    // B-load mapping: 8 scalars -> 4 kp per thread
    const int bcol = tid & 127;
    const int bkpq = tid >> 7;          // 0..3 (k offset bkpq*8)

    const uint32_t a_s0 = smem_u32(&Asp[0][ar * PAD + aq * 4]);
    const uint32_t a_s1 = smem_u32(&Asp[1][ar * PAD + aq * 4]);

    ull acc[8][4];
#pragma unroll
    for (int i = 0; i < 8; i++)
#pragma unroll
        for (int j = 0; j < 4; j++) acc[i][j] = 0ULL;

    const int agrow = row0 + ar;
    const float* a_gp = E + (size_t)agrow * LATDIM + aq * 8;

    // ---- prologue: A chunk 0 via cp.async; B chunk 0 via LDG regs ----
    if (agrow < N) {
        CP_ASYNC16(a_s0,      a_gp);
        CP_ASYNC16(a_s0 + 16, a_gp + 4);
    } else {
        ulonglong2 z = make_ulonglong2(0ULL, 0ULL);
        *(ulonglong2*)&Asp[0][ar * PAD + aq * 4]     = z;
        *(ulonglong2*)&Asp[0][ar * PAD + aq * 4 + 2] = z;
    }
    CP_COMMIT();

    float bw[8];
    {
        const float* wp = W + (size_t)(bkpq * 8) * LATDIM + bcol;
#pragma unroll
        for (int m = 0; m < 8; m++) bw[m] = __ldg(wp + m * LATDIM);
    }
    // pack + store B chunk 0
    {
        ull* d = &Bsp[0][bcol * PAD + bkpq * 4];
        *(ulonglong2*)d       = make_ulonglong2(pack2(bw[0], bw[1]), pack2(bw[2], bw[3]));
        *(ulonglong2*)(d + 2) = make_ulonglong2(pack2(bw[4], bw[5]), pack2(bw[6], bw[7]));
    }

    for (int c = 0; c < 4; c++) {
        const int cur = c & 1;

        // issue next chunk's loads
        if (c < 3) {
            const int kcn = (c + 1) * 32;
            const uint32_t a_sn = (cur ? a_s0 : a_s1);
            if (agrow < N) {
                const float* gp = a_gp + kcn;
                CP_ASYNC16(a_sn,      gp);
                CP_ASYNC16(a_sn + 16, gp + 4);
            }
            CP_COMMIT();
            const float* wp = W + (size_t)(kcn + bkpq * 8) * LATDIM + bcol;
#pragma unroll
            for (int m = 0; m < 8; m++) bw[m] = __ldg(wp + m * LATDIM);
            CP_WAIT1();     // chunk c's A group complete (c+1 in flight)
        } else {
            CP_WAIT0();
        }
        __syncthreads();    // A buf cur ready for all; B buf cur stored last iter

        const ull* Ab = Asp[cur];
        const ull* Bb = Bsp[cur];
#pragma unroll
        for (int kp2 = 0; kp2 < 8; kp2++) {
            ulonglong2 a[8];
#pragma unroll
            for (int i = 0; i < 8; i++)
                a[i] = *(const ulonglong2*)&Ab[(tidr * 8 + i) * PAD + kp2 * 2];
#pragma unroll
            for (int j = 0; j < 4; j++) {
                ulonglong2 b = *(const ulonglong2*)&Bb[(tidc + j * 32) * PAD + kp2 * 2];
#pragma unroll
                for (int i = 0; i < 8; i++) {
                    fma2(acc[i][j], a[i].x, b.x);
                    fma2(acc[i][j], a[i].y, b.y);
                }
            }
        }

        // store next chunk's B (LDG latency now covered by the FMA block)
        if (c < 3) {
            ull* d = &Bsp[cur ^ 1][bcol * PAD + bkpq * 4];
            *(ulonglong2*)d       = make_ulonglong2(pack2(bw[0], bw[1]), pack2(bw[2], bw[3]));
            *(ulonglong2*)(d + 2) = make_ulonglong2(pack2(bw[4], bw[5]), pack2(bw[6], bw[7]));
        }
        __syncthreads();    // compute on buf cur done before it is refilled
    }

    // epilogue: out[row0 + tidr*8 + i][tidc + j*32] = lo + hi
#pragma unroll
    for (int i = 0; i < 8; i++) {
        int grow = row0 + tidr * 8 + i;
        if (grow < N) {
            float* dst = Out + (size_t)grow * LATDIM + tidc;
#pragma unroll
            for (int j = 0; j < 4; j++) {
                float lo, hi;
                unpack2(acc[i][j], lo, hi);
                dst[j * 32] = lo + hi;
            }
        }
    }
}

// ============================================================
// Single-launch exclusive scan with inter-block lookback (49 blocks,
// all co-resident: 49 < 148 SMs, spin-wait deadlock-free).
// ============================================================
__global__ __launch_bounds__(1024)
void scan_fused(int n) {
    __shared__ int warp_sums[32];
    __shared__ int s_offset;
    const int tid  = threadIdx.x;
    const int lane = tid & 31;
    const int wid  = tid >> 5;
    const int bid  = blockIdx.x;
    const int i    = bid * 1024 + tid;

    int v = (i < n) ? g_cnt[i] : 0;

    int s = v;
#pragma unroll
    for (int o = 1; o < 32; o <<= 1) {
        int t = __shfl_up_sync(0xffffffffu, s, o);
        if (lane >= o) s += t;
    }
    if (lane == 31) warp_sums[wid] = s;
    __syncthreads();
    if (wid == 0) {
        int w = warp_sums[lane];
#pragma unroll
        for (int o = 1; o < 32; o <<= 1) {
            int t = __shfl_up_sync(0xffffffffu, w, o);
            if (lane >= o) w += t;
        }
        warp_sums[lane] = w;
    }
    __syncthreads();
    int incl = s + (wid > 0 ? warp_sums[wid - 1] : 0);

    if (tid == 1023) atomicExch(&g_bsum[bid], incl + 1);
    if (tid == 0) s_offset = 0;
    __syncthreads();

    if (tid < bid) {
        int pv;
        do { pv = atomicAdd(&g_bsum[tid], 0); } while (pv == 0);
        atomicAdd(&s_offset, pv - 1);
    }
    __syncthreads();

    int r = s_offset + incl - v;
    if (i < n) {
        g_rowptr[i] = r;
        g_fill[i]   = r;
        g_cnt[i]    = 0;           // re-zero for next call's fused histogram
    } else if (i == n) {
        g_rowptr[n] = r;
    }
}

__global__ void scatter_kernel(const int* __restrict__ rows,
                               const int* __restrict__ cols, int nE) {
    int e = blockIdx.x * blockDim.x + threadIdx.x;
    if (e < 64) g_bsum[e] = 0;     // reset lookback slots for next call
    if (e < nE) {
        int r = rows[e];
        int pos = atomicAdd(&g_fill[r], 1);
        g_adj[pos] = cols[e];
    }
}

// ============================================================
// Kernel 2: fused per-node attention. One warp per node, 2-edge unroll.
// ============================================================
__global__ void attn_kernel(float* __restrict__ out, int N) {
    int warp = (blockIdx.x * blockDim.x + threadIdx.x) >> 5;
    int lane = threadIdx.x & 31;
    if (warp >= N) return;

    const float4 q = __ldg((const float4*)(g_Q + (size_t)warp * LATDIM) + lane);
    int beg = g_rowptr[warp];
    int end = g_rowptr[warp + 1];

    float ax = 0.f, ay = 0.f, az = 0.f, aw = 0.f, denom = 0.f;

    int i = beg;
    for (; i + 2 <= end; i += 2) {
        int c0 = __ldg(g_adj + i);
        int c1 = __ldg(g_adj + i + 1);
        const float4 k0 = __ldg((const float4*)(g_K + (size_t)c0 * LATDIM) + lane);
        const float4 v0 = __ldg((const float4*)(g_V + (size_t)c0 * LATDIM) + lane);
        const float4 k1 = __ldg((const float4*)(g_K + (size_t)c1 * LATDIM) + lane);
        const float4 v1 = __ldg((const float4*)(g_V + (size_t)c1 * LATDIM) + lane);

        float p0 = q.x * k0.x + q.y * k0.y + q.z * k0.z + q.w * k0.w;
        float p1 = q.x * k1.x + q.y * k1.y + q.z * k1.z + q.w * k1.w;
        p0 += __shfl_xor_sync(0xffffffffu, p0, 1);
        p1 += __shfl_xor_sync(0xffffffffu, p1, 1);
        p0 += __shfl_xor_sync(0xffffffffu, p0, 2);
        p1 += __shfl_xor_sync(0xffffffffu, p1, 2);
        p0 += __shfl_xor_sync(0xffffffffu, p0, 4);
        p1 += __shfl_xor_sync(0xffffffffu, p1, 4);
        p0 = fminf(fmaxf(p0, -10.f), 10.f);
        p1 = fminf(fmaxf(p1, -10.f), 10.f);
        float e0 = __expf(p0);
        float e1 = __expf(p1);
        denom += e0 + e1;
        ax = fmaf(e0, v0.x, ax); ax = fmaf(e1, v1.x, ax);
        ay = fmaf(e0, v0.y, ay); ay = fmaf(e1, v1.y, ay);
        az = fmaf(e0, v0.z, az); az = fmaf(e1, v1.z, az);
        aw = fmaf(e0, v0.w, aw); aw = fmaf(e1, v1.w, aw);
    }
    if (i < end) {
        int c = __ldg(g_adj + i);
        const float4 k4 = __ldg((const float4*)(g_K + (size_t)c * LATDIM) + lane);
        const float4 v4 = __ldg((const float4*)(g_V + (size_t)c * LATDIM) + lane);
        float p = q.x * k4.x + q.y * k4.y + q.z * k4.z + q.w * k4.w;
        p += __shfl_xor_sync(0xffffffffu, p, 1);
        p += __shfl_xor_sync(0xffffffffu, p, 2);
        p += __shfl_xor_sync(0xffffffffu, p, 4);
        p = fminf(fmaxf(p, -10.f), 10.f);
        float e = __expf(p);
        denom += e;
        ax = fmaf(e, v4.x, ax);
        ay = fmaf(e, v4.y, ay);
        az = fmaf(e, v4.z, az);
        aw = fmaf(e, v4.w, aw);
    }

    float inv = 1.f / (denom + 1e-8f);
    float4 o = make_float4(ax * inv, ay * inv, az * inv, aw * inv);
    *((float4*)out + (size_t)warp * 32 + lane) = o;
}

// ============================================================
extern "C" void kernel_launch(void* const* d_in, const int* in_sizes, int n_in,
                              void* d_out, int out_size) {
    const float* E    = (const float*)d_in[0];
    const float* qW   = (const float*)d_in[1];
    const float* kW   = (const float*)d_in[2];
    const float* vW   = (const float*)d_in[3];
    const int*   rows = (const int*)d_in[4];
    const int*   cols = (const int*)d_in[5];

    int N  = in_sizes[0] / LATDIM;
    int Eg = in_sizes[4];

    int nb = (N + 1023) / 1024;   // 49 blocks — all co-resident

    dim3 gg((N + 127) / 128, 4);
    gemm3_hist_kernel<<<gg, 512>>>(E, qW, kW, vW, rows, N, Eg);   // 1
    scan_fused<<<nb, 1024>>>(N);                                  // 2
    scatter_kernel<<<(Eg + 255) / 256, 256>>>(rows, cols, Eg);    // 3
    attn_kernel<<<(N + 7) / 8, 256>>>((float*)d_out, N);          // 4 <- ncu slot
}

// round 13
// speedup vs baseline: 1.0624x; 1.0624x over previous
#include <cuda_runtime.h>
#include <cuda_bf16.h>
#include <cstdint>

#define N_NODES 50000
#define N_EDGES 800000
#define LATDIM  128
#define PAD     18          // ull stride per row/col in smem (bank-conflict-free)

typedef unsigned long long ull;

// ---- scratch (static device globals: the sanctioned no-alloc workaround) ----
__device__ float g_Q[N_NODES * LATDIM];
__device__ float g_K[N_NODES * LATDIM];
__device__ float g_V[N_NODES * LATDIM];
__device__ int   g_cnt[N_NODES];       // zero-init; re-zeroed by scan each run
__device__ int   g_bsum[64];           // lookback slots: 0 = unpublished, else total+1
__device__ int   g_rowptr[N_NODES + 1];
__device__ int   g_fill[N_NODES];
__device__ int   g_adj[N_EDGES];

// ---- packed f32x2 helpers (base sm_103 PTX — no 'a' features) ----
__device__ __forceinline__ ull pack2(float lo, float hi) {
    ull r;
    asm("mov.b64 %0, {%1, %2};" : "=l"(r)
        : "r"(__float_as_uint(lo)), "r"(__float_as_uint(hi)));
    return r;
}
__device__ __forceinline__ void fma2(ull& d, ull a, ull b) {
    asm("fma.rn.f32x2 %0, %1, %2, %3;" : "=l"(d) : "l"(a), "l"(b), "l"(d));
}
__device__ __forceinline__ void unpack2(ull v, float& lo, float& hi) {
    unsigned ulo, uhi;
    asm("mov.b64 {%0, %1}, %2;" : "=r"(ulo), "=r"(uhi) : "l"(v));
    lo = __uint_as_float(ulo);
    hi = __uint_as_float(uhi);
}
__device__ __forceinline__ uint32_t smem_u32(const void* p) {
    uint32_t a;
    asm("{ .reg .u64 t; cvta.to.shared.u64 t, %1; cvt.u32.u64 %0, t; }"
        : "=r"(a) : "l"(p));
    return a;
}
#define CP_ASYNC16(dst_u32, src) \
    asm volatile("cp.async.ca.shared.global [%0], [%1], 16;" \
                 :: "r"(dst_u32), "l"(src) : "memory")
#define CP_COMMIT() asm volatile("cp.async.commit_group;" ::: "memory")
#define CP_WAIT1()  asm volatile("cp.async.wait_group 1;" ::: "memory")
#define CP_WAIT0()  asm volatile("cp.async.wait_group 0;" ::: "memory")

// ============================================================
// Kernel 1: fused Q/K/V projection + edge histogram.
// grid = (ceil(N/128), 7): y<6 GEMM (matrix y>>1, col-half y&1),
// y==6 histogram (fills the GEMM tail wave).
//
// k-pair FFMA2 scheme at OCCUPANCY 2 (R12's occ-1 single-block sync
// serialization was the regression): tile 128 rows x 64 cols, 256
// threads, 54KB smem -> 2 blocks/SM so syncs/waits overlap across
// blocks. acc f32x2 lanes = {even-k, odd-k} partial sums; both FFMA2
// operands are natural k-adjacent memory pairs -> ZERO pack MOVs in
// the mainloop. Per 4k per thread: 64 FFMA2 + 12 LDS (fma ~84% of
// slots vs 59% in the scalar version).
// ============================================================
__global__ __launch_bounds__(256, 2)
void gemm3_hist_kernel(const float* __restrict__ E,
                       const float* __restrict__ qW,
                       const float* __restrict__ kW,
                       const float* __restrict__ vW,
                       const int* __restrict__ rows,
                       int N, int nE)
{
    // --- histogram slice: scheduled after GEMM blocks ---
    if (blockIdx.y == 6) {
        int stride = gridDim.x * blockDim.x;
        for (int e = blockIdx.x * blockDim.x + threadIdx.x; e < nE; e += stride)
            atomicAdd(&g_cnt[rows[e]], 1);
        return;
    }

    __shared__ ull Asp[2][128 * PAD];   // [buf][row*PAD + kp]   2 x 18KB
    __shared__ ull Bsp[2][64 * PAD];    // [buf][col*PAD + kp]   2 x 9KB

    const int m  = blockIdx.y >> 1;     // matrix 0..2
    const int ch = blockIdx.y & 1;      // col half: cols [ch*64, ch*64+64)
    const float* W   = (m == 0) ? qW : (m == 1 ? kW : vW);
    float*       Out = (m == 0) ? g_Q : (m == 1 ? g_K : g_V);

    const int row0 = blockIdx.x * 128;
    const int tid  = threadIdx.x;
    const int tidc = tid & 15;          // cols: ch*64 + tidc + {0,16,32,48}
    const int tidr = tid >> 4;          // rows: tidr*8 .. +8

    // A-load mapping: 8 ull (=64B) per thread per chunk
    const int ar = tid >> 1;            // row 0..127
    const int aq = tid & 1;             // half-row: ull offset aq*8, k offset aq*16
    // B-load mapping: 8 scalars (8 consecutive k) -> 4 kp per thread
    const int bcol = tid & 63;          // col within half
    const int bkpq = tid >> 6;          // 0..3: kp offset bkpq*4, k offset bkpq*8

    const uint32_t a_s0 = smem_u32(&Asp[0][ar * PAD + aq * 8]);
    const uint32_t a_s1 = smem_u32(&Asp[1][ar * PAD + aq * 8]);

    ull acc[8][4];
#pragma unroll
    for (int i = 0; i < 8; i++)
#pragma unroll
        for (int j = 0; j < 4; j++) acc[i][j] = 0ULL;

    const int agrow = row0 + ar;
    const float* a_gp = E + (size_t)agrow * LATDIM + aq * 16;
    const float* w_gp = W + ch * 64 + bcol;

    // ---- prologue: A chunk 0 via cp.async; B chunk 0 via LDG regs ----
    if (agrow < N) {
        CP_ASYNC16(a_s0,      a_gp);
        CP_ASYNC16(a_s0 + 16, a_gp + 4);
        CP_ASYNC16(a_s0 + 32, a_gp + 8);
        CP_ASYNC16(a_s0 + 48, a_gp + 12);
    } else {
        ulonglong2 z = make_ulonglong2(0ULL, 0ULL);
#pragma unroll
        for (int u = 0; u < 4; u++)
            *(ulonglong2*)&Asp[0][ar * PAD + aq * 8 + u * 2] = z;
    }
    CP_COMMIT();

    float bw[8];
    {
        const float* wp = w_gp + (size_t)(bkpq * 8) * LATDIM;
#pragma unroll
        for (int q = 0; q < 8; q++) bw[q] = __ldg(wp + q * LATDIM);
    }
    {
        ull* d = &Bsp[0][bcol * PAD + bkpq * 4];
        *(ulonglong2*)d       = make_ulonglong2(pack2(bw[0], bw[1]), pack2(bw[2], bw[3]));
        *(ulonglong2*)(d + 2) = make_ulonglong2(pack2(bw[4], bw[5]), pack2(bw[6], bw[7]));
    }

    for (int c = 0; c < 4; c++) {
        const int cur = c & 1;

        if (c < 3) {
            const int kcn = (c + 1) * 32;
            const uint32_t a_sn = (cur ? a_s0 : a_s1);
            if (agrow < N) {
                const float* gp = a_gp + kcn;
                CP_ASYNC16(a_sn,      gp);
                CP_ASYNC16(a_sn + 16, gp + 4);
                CP_ASYNC16(a_sn + 32, gp + 8);
                CP_ASYNC16(a_sn + 48, gp + 12);
            }
            CP_COMMIT();
            const float* wp = w_gp + (size_t)(kcn + bkpq * 8) * LATDIM;
#pragma unroll
            for (int q = 0; q < 8; q++) bw[q] = __ldg(wp + q * LATDIM);
            CP_WAIT1();     // chunk c's A group complete (c+1 in flight)
        } else {
            CP_WAIT0();
        }
        __syncthreads();    // A buf cur ready; B buf cur stored last iter

        const ull* Ab = Asp[cur];
        const ull* Bb = Bsp[cur];
#pragma unroll
        for (int kp2 = 0; kp2 < 8; kp2++) {
            ulonglong2 a[8];
#pragma unroll
            for (int i = 0; i < 8; i++)
                a[i] = *(const ulonglong2*)&Ab[(tidr * 8 + i) * PAD + kp2 * 2];
#pragma unroll
            for (int j = 0; j < 4; j++) {
                ulonglong2 b = *(const ulonglong2*)&Bb[(tidc + j * 16) * PAD + kp2 * 2];
#pragma unroll
                for (int i = 0; i < 8; i++) {
                    fma2(acc[i][j], a[i].x, b.x);
                    fma2(acc[i][j], a[i].y, b.y);
                }
            }
        }

        // store next chunk's B (LDG latency covered by the FMA block above)
        if (c < 3) {
            ull* d = &Bsp[cur ^ 1][bcol * PAD + bkpq * 4];
            *(ulonglong2*)d       = make_ulonglong2(pack2(bw[0], bw[1]), pack2(bw[2], bw[3]));
            *(ulonglong2*)(d + 2) = make_ulonglong2(pack2(bw[4], bw[5]), pack2(bw[6], bw[7]));
        }
        __syncthreads();    // compute on buf cur done before it is refilled
    }

    // epilogue: out[row0 + tidr*8 + i][ch*64 + tidc + j*16] = lo + hi
#pragma unroll
    for (int i = 0; i < 8; i++) {
        int grow = row0 + tidr * 8 + i;
        if (grow < N) {
            float* dst = Out + (size_t)grow * LATDIM + ch * 64 + tidc;
#pragma unroll
            for (int j = 0; j < 4; j++) {
                float lo, hi;
                unpack2(acc[i][j], lo, hi);
                dst[j * 16] = lo + hi;
            }
        }
    }
}

// ============================================================
// Single-launch exclusive scan with inter-block lookback (49 blocks,
// all co-resident: 49 < 148 SMs, spin-wait deadlock-free).
// ============================================================
__global__ __launch_bounds__(1024)
void scan_fused(int n) {
    __shared__ int warp_sums[32];
    __shared__ int s_offset;
    const int tid  = threadIdx.x;
    const int lane = tid & 31;
    const int wid  = tid >> 5;
    const int bid  = blockIdx.x;
    const int i    = bid * 1024 + tid;

    int v = (i < n) ? g_cnt[i] : 0;

    int s = v;
#pragma unroll
    for (int o = 1; o < 32; o <<= 1) {
        int t = __shfl_up_sync(0xffffffffu, s, o);
        if (lane >= o) s += t;
    }
    if (lane == 31) warp_sums[wid] = s;
    __syncthreads();
    if (wid == 0) {
        int w = warp_sums[lane];
#pragma unroll
        for (int o = 1; o < 32; o <<= 1) {
            int t = __shfl_up_sync(0xffffffffu, w, o);
            if (lane >= o) w += t;
        }
        warp_sums[lane] = w;
    }
    __syncthreads();
    int incl = s + (wid > 0 ? warp_sums[wid - 1] : 0);

    if (tid == 1023) atomicExch(&g_bsum[bid], incl + 1);
    if (tid == 0) s_offset = 0;
    __syncthreads();

    if (tid < bid) {
        int pv;
        do { pv = atomicAdd(&g_bsum[tid], 0); } while (pv == 0);
        atomicAdd(&s_offset, pv - 1);
    }
    __syncthreads();

    int r = s_offset + incl - v;
    if (i < n) {
        g_rowptr[i] = r;
        g_fill[i]   = r;
        g_cnt[i]    = 0;           // re-zero for next call's fused histogram
    } else if (i == n) {
        g_rowptr[n] = r;
    }
}

__global__ void scatter_kernel(const int* __restrict__ rows,
                               const int* __restrict__ cols, int nE) {
    int e = blockIdx.x * blockDim.x + threadIdx.x;
    if (e < 64) g_bsum[e] = 0;     // reset lookback slots for next call
    if (e < nE) {
        int r = rows[e];
        int pos = atomicAdd(&g_fill[r], 1);
        g_adj[pos] = cols[e];
    }
}

// ============================================================
// Kernel 2: fused per-node attention. One warp per node, 2-edge unroll.
// ============================================================
__global__ void attn_kernel(float* __restrict__ out, int N) {
    int warp = (blockIdx.x * blockDim.x + threadIdx.x) >> 5;
    int lane = threadIdx.x & 31;
    if (warp >= N) return;

    const float4 q = __ldg((const float4*)(g_Q + (size_t)warp * LATDIM) + lane);
    int beg = g_rowptr[warp];
    int end = g_rowptr[warp + 1];

    float ax = 0.f, ay = 0.f, az = 0.f, aw = 0.f, denom = 0.f;

    int i = beg;
    for (; i + 2 <= end; i += 2) {
        int c0 = __ldg(g_adj + i);
        int c1 = __ldg(g_adj + i + 1);
        const float4 k0 = __ldg((const float4*)(g_K + (size_t)c0 * LATDIM) + lane);
        const float4 v0 = __ldg((const float4*)(g_V + (size_t)c0 * LATDIM) + lane);
        const float4 k1 = __ldg((const float4*)(g_K + (size_t)c1 * LATDIM) + lane);
        const float4 v1 = __ldg((const float4*)(g_V + (size_t)c1 * LATDIM) + lane);

        float p0 = q.x * k0.x + q.y * k0.y + q.z * k0.z + q.w * k0.w;
        float p1 = q.x * k1.x + q.y * k1.y + q.z * k1.z + q.w * k1.w;
        p0 += __shfl_xor_sync(0xffffffffu, p0, 1);
        p1 += __shfl_xor_sync(0xffffffffu, p1, 1);
        p0 += __shfl_xor_sync(0xffffffffu, p0, 2);
        p1 += __shfl_xor_sync(0xffffffffu, p1, 2);
        p0 += __shfl_xor_sync(0xffffffffu, p0, 4);
        p1 += __shfl_xor_sync(0xffffffffu, p1, 4);
        p0 = fminf(fmaxf(p0, -10.f), 10.f);
        p1 = fminf(fmaxf(p1, -10.f), 10.f);
        float e0 = __expf(p0);
        float e1 = __expf(p1);
        denom += e0 + e1;
        ax = fmaf(e0, v0.x, ax); ax = fmaf(e1, v1.x, ax);
        ay = fmaf(e0, v0.y, ay); ay = fmaf(e1, v1.y, ay);
        az = fmaf(e0, v0.z, az); az = fmaf(e1, v1.z, az);
        aw = fmaf(e0, v0.w, aw); aw = fmaf(e1, v1.w, aw);
    }
    if (i < end) {
        int c = __ldg(g_adj + i);
        const float4 k4 = __ldg((const float4*)(g_K + (size_t)c * LATDIM) + lane);
        const float4 v4 = __ldg((const float4*)(g_V + (size_t)c * LATDIM) + lane);
        float p = q.x * k4.x + q.y * k4.y + q.z * k4.z + q.w * k4.w;
        p += __shfl_xor_sync(0xffffffffu, p, 1);
        p += __shfl_xor_sync(0xffffffffu, p, 2);
        p += __shfl_xor_sync(0xffffffffu, p, 4);
        p = fminf(fmaxf(p, -10.f), 10.f);
        float e = __expf(p);
        denom += e;
        ax = fmaf(e, v4.x, ax);
        ay = fmaf(e, v4.y, ay);
        az = fmaf(e, v4.z, az);
        aw = fmaf(e, v4.w, aw);
    }

    float inv = 1.f / (denom + 1e-8f);
    float4 o = make_float4(ax * inv, ay * inv, az * inv, aw * inv);
    *((float4*)out + (size_t)warp * 32 + lane) = o;
}

// ============================================================
extern "C" void kernel_launch(void* const* d_in, const int* in_sizes, int n_in,
                              void* d_out, int out_size) {
    const float* E    = (const float*)d_in[0];
    const float* qW   = (const float*)d_in[1];
    const float* kW   = (const float*)d_in[2];
    const float* vW   = (const float*)d_in[3];
    const int*   rows = (const int*)d_in[4];
    const int*   cols = (const int*)d_in[5];

    int N  = in_sizes[0] / LATDIM;
    int Eg = in_sizes[4];

    int nb = (N + 1023) / 1024;   // 49 blocks — all co-resident

    dim3 gg((N + 127) / 128, 7);  // y<6: GEMM (3 mat x 2 col-halves), y==6: hist
    gemm3_hist_kernel<<<gg, 256>>>(E, qW, kW, vW, rows, N, Eg);   // 1
    scan_fused<<<nb, 1024>>>(N);                                  // 2
    scatter_kernel<<<(Eg + 255) / 256, 256>>>(rows, cols, Eg);    // 3
    attn_kernel<<<(N + 7) / 8, 256>>>((float*)d_out, N);          // 4 <- ncu slot
}

// round 14
// speedup vs baseline: 1.2042x; 1.1335x over previous
#include <cuda_runtime.h>
#include <cuda_bf16.h>

#define N_NODES 50000
#define N_EDGES 800000
#define LATDIM  128

typedef unsigned long long ull;

// ---- scratch (static device globals: the sanctioned no-alloc workaround) ----
__device__ float g_Q[N_NODES * LATDIM];
__device__ float g_K[N_NODES * LATDIM];
__device__ float g_V[N_NODES * LATDIM];
__device__ int   g_cnt[N_NODES];       // zero-init; re-zeroed by scan each run
__device__ int   g_bsum[64];           // lookback slots: 0 = unpublished, else total+1
__device__ int   g_rowptr[N_NODES + 1];
__device__ int   g_fill[N_NODES];
__device__ int   g_adj[N_EDGES];

// ---- packed f32x2 helpers (base sm_103 PTX — no 'a' features) ----
__device__ __forceinline__ ull pack2(float lo, float hi) {
    ull r;
    asm("mov.b64 %0, {%1, %2};" : "=l"(r)
        : "r"(__float_as_uint(lo)), "r"(__float_as_uint(hi)));
    return r;
}
__device__ __forceinline__ void fma2(ull& d, ull a, ull b) {
    asm("fma.rn.f32x2 %0, %1, %2, %3;" : "=l"(d) : "l"(a), "l"(b), "l"(d));
}
__device__ __forceinline__ void unpack2(ull v, float& lo, float& hi) {
    unsigned ulo, uhi;
    asm("mov.b64 {%0, %1}, %2;" : "=r"(ulo), "=r"(uhi) : "l"(v));
    lo = __uint_as_float(ulo);
    hi = __uint_as_float(uhi);
}

// ============================================================
// Kernel 1: fused Q/K/V projection + edge histogram (R10 version —
// measured 104us; the k-pair variants R12/R13 both regressed due to
// A-operand crossbar wavefront inflation. This is the locked-in GEMM.)
// grid = (ceil(N/128), 4): y<3 GEMM slices, y==3 histogram.
// ============================================================
__global__ __launch_bounds__(256, 2)
void gemm3_hist_kernel(const float* __restrict__ E,
                       const float* __restrict__ qW,
                       const float* __restrict__ kW,
                       const float* __restrict__ vW,
                       const int* __restrict__ rows,
                       int N, int nE)
{
    // --- histogram slice: scheduled after GEMM blocks, fills the tail wave ---
    if (blockIdx.y == 3) {
        int stride = gridDim.x * blockDim.x;
        for (int e = blockIdx.x * blockDim.x + threadIdx.x; e < nE; e += stride)
            atomicAdd(&g_cnt[rows[e]], 1);
        return;
    }

    __shared__ float As[32][132];   // A tile transposed: As[k][row]
    __shared__ float Bs[32][128];   // W tile: Bs[k][col]

    const float* W   = (blockIdx.y == 0) ? qW : (blockIdx.y == 1 ? kW : vW);
    float*       Out = (blockIdx.y == 0) ? g_Q : (blockIdx.y == 1 ? g_K : g_V);

    const int row0 = blockIdx.x * 128;
    const int tid  = threadIdx.x;
    const int tr   = (tid >> 4) << 3;   // thread row base (0..120)
    const int tc   = (tid & 15) << 2;   // col blocks [tc,tc+4) and [tc+64,tc+68)
    const int kq   = (tid & 7) * 4;     // A-load k offset
    const int rb   = tid >> 3;          // A-load row base

    ull acc[8][4];
#pragma unroll
    for (int i = 0; i < 8; i++)
#pragma unroll
        for (int j = 0; j < 4; j++) acc[i][j] = 0ULL;

    // prefetch A chunk 0 into registers
    float4 aq[4];
#pragma unroll
    for (int rr = 0; rr < 4; rr++) {
        int grow = row0 + rb + rr * 32;
        aq[rr] = (grow < N)
            ? __ldg((const float4*)(E + (size_t)grow * LATDIM + kq))
            : make_float4(0.f, 0.f, 0.f, 0.f);
    }

    for (int c = 0; c < 4; c++) {
        const int kc = c * 32;
        __syncthreads();                // previous chunk's compute fully done

        // B chunk load + store (W is L2-resident after wave 1)
#pragma unroll
        for (int v = tid; v < 32 * 32; v += 256) {
            int k = v >> 5, c4 = v & 31;
            *(float4*)&Bs[k][c4 * 4] =
                __ldg((const float4*)(W + (size_t)(kc + k) * LATDIM) + c4);
        }
        // A chunk store from prefetched registers (transposed)
#pragma unroll
        for (int rr = 0; rr < 4; rr++) {
            int r = rb + rr * 32;
            As[kq + 0][r] = aq[rr].x;
            As[kq + 1][r] = aq[rr].y;
            As[kq + 2][r] = aq[rr].z;
            As[kq + 3][r] = aq[rr].w;
        }
        __syncthreads();

        // issue next chunk's A LDGs now — latency hides under compute below
        if (c < 3) {
#pragma unroll
            for (int rr = 0; rr < 4; rr++) {
                int grow = row0 + rb + rr * 32;
                aq[rr] = (grow < N)
                    ? __ldg((const float4*)(E + (size_t)grow * LATDIM + kc + 32 + kq))
                    : make_float4(0.f, 0.f, 0.f, 0.f);
            }
        }

#pragma unroll 8
        for (int k = 0; k < 32; k++) {
            float4 a0 = *(const float4*)&As[k][tr];        // broadcast
            float4 a1 = *(const float4*)&As[k][tr + 4];    // broadcast
            ulonglong2 bq0 = *(const ulonglong2*)&Bs[k][tc];       // contiguous
            ulonglong2 bq1 = *(const ulonglong2*)&Bs[k][tc + 64];  // contiguous
            ull bb[4] = {bq0.x, bq0.y, bq1.x, bq1.y};
            ull aa[8];
            aa[0] = pack2(a0.x, a0.x); aa[1] = pack2(a0.y, a0.y);
            aa[2] = pack2(a0.z, a0.z); aa[3] = pack2(a0.w, a0.w);
            aa[4] = pack2(a1.x, a1.x); aa[5] = pack2(a1.y, a1.y);
            aa[6] = pack2(a1.z, a1.z); aa[7] = pack2(a1.w, a1.w);
#pragma unroll
            for (int i = 0; i < 8; i++) {
                fma2(acc[i][0], aa[i], bb[0]);
                fma2(acc[i][1], aa[i], bb[1]);
                fma2(acc[i][2], aa[i], bb[2]);
                fma2(acc[i][3], aa[i], bb[3]);
            }
        }
    }

#pragma unroll
    for (int i = 0; i < 8; i++) {
        int grow = row0 + tr + i;
        if (grow < N) {
            float o[8];
#pragma unroll
            for (int j = 0; j < 4; j++) unpack2(acc[i][j], o[2 * j], o[2 * j + 1]);
            *(float4*)(Out + (size_t)grow * LATDIM + tc)      = make_float4(o[0], o[1], o[2], o[3]);
            *(float4*)(Out + (size_t)grow * LATDIM + tc + 64) = make_float4(o[4], o[5], o[6], o[7]);
        }
    }
}

// ============================================================
// Single-launch exclusive scan with inter-block lookback (49 blocks,
// all co-resident: 49 < 148 SMs, spin-wait deadlock-free).
// ============================================================
__global__ __launch_bounds__(1024)
void scan_fused(int n) {
    __shared__ int warp_sums[32];
    __shared__ int s_offset;
    const int tid  = threadIdx.x;
    const int lane = tid & 31;
    const int wid  = tid >> 5;
    const int bid  = blockIdx.x;
    const int i    = bid * 1024 + tid;

    int v = (i < n) ? g_cnt[i] : 0;

    int s = v;
#pragma unroll
    for (int o = 1; o < 32; o <<= 1) {
        int t = __shfl_up_sync(0xffffffffu, s, o);
        if (lane >= o) s += t;
    }
    if (lane == 31) warp_sums[wid] = s;
    __syncthreads();
    if (wid == 0) {
        int w = warp_sums[lane];
#pragma unroll
        for (int o = 1; o < 32; o <<= 1) {
            int t = __shfl_up_sync(0xffffffffu, w, o);
            if (lane >= o) w += t;
        }
        warp_sums[lane] = w;
    }
    __syncthreads();
    int incl = s + (wid > 0 ? warp_sums[wid - 1] : 0);

    if (tid == 1023) atomicExch(&g_bsum[bid], incl + 1);
    if (tid == 0) s_offset = 0;
    __syncthreads();

    if (tid < bid) {
        int pv;
        do { pv = atomicAdd(&g_bsum[tid], 0); } while (pv == 0);
        atomicAdd(&s_offset, pv - 1);
    }
    __syncthreads();

    int r = s_offset + incl - v;
    if (i < n) {
        g_rowptr[i] = r;
        g_fill[i]   = r;
        g_cnt[i]    = 0;           // re-zero for next call's fused histogram
    } else if (i == n) {
        g_rowptr[n] = r;
    }
}

__global__ void scatter_kernel(const int* __restrict__ rows,
                               const int* __restrict__ cols, int nE) {
    int e = blockIdx.x * blockDim.x + threadIdx.x;
    if (e < 64) g_bsum[e] = 0;     // reset lookback slots for next call
    if (e < nE) {
        int r = rows[e];
        int pos = atomicAdd(&g_fill[r], 1);
        g_adj[pos] = cols[e];
    }
}

// ============================================================
// Kernel 2: fused per-node attention. One warp per node.
// 4-edge unroll: 8 independent LDG.128 in flight per iteration
// (R4->R8 showed 2-edge unroll gave -8us; issue=45% + L2=61% says
// latency exposure remains — this tests whether more MLP converts it).
// ============================================================
__global__ void attn_kernel(float* __restrict__ out, int N) {
    int warp = (blockIdx.x * blockDim.x + threadIdx.x) >> 5;
    int lane = threadIdx.x & 31;
    if (warp >= N) return;

    const float4 q = __ldg((const float4*)(g_Q + (size_t)warp * LATDIM) + lane);
    int beg = g_rowptr[warp];
    int end = g_rowptr[warp + 1];

    float ax = 0.f, ay = 0.f, az = 0.f, aw = 0.f, denom = 0.f;

    int i = beg;
    for (; i + 4 <= end; i += 4) {
        int c0 = __ldg(g_adj + i);
        int c1 = __ldg(g_adj + i + 1);
        int c2 = __ldg(g_adj + i + 2);
        int c3 = __ldg(g_adj + i + 3);
        const float4 k0 = __ldg((const float4*)(g_K + (size_t)c0 * LATDIM) + lane);
        const float4 k1 = __ldg((const float4*)(g_K + (size_t)c1 * LATDIM) + lane);
        const float4 k2 = __ldg((const float4*)(g_K + (size_t)c2 * LATDIM) + lane);
        const float4 k3 = __ldg((const float4*)(g_K + (size_t)c3 * LATDIM) + lane);
        const float4 v0 = __ldg((const float4*)(g_V + (size_t)c0 * LATDIM) + lane);
        const float4 v1 = __ldg((const float4*)(g_V + (size_t)c1 * LATDIM) + lane);
        const float4 v2 = __ldg((const float4*)(g_V + (size_t)c2 * LATDIM) + lane);
        const float4 v3 = __ldg((const float4*)(g_V + (size_t)c3 * LATDIM) + lane);

        float p0 = q.x * k0.x + q.y * k0.y + q.z * k0.z + q.w * k0.w;
        float p1 = q.x * k1.x + q.y * k1.y + q.z * k1.z + q.w * k1.w;
        float p2 = q.x * k2.x + q.y * k2.y + q.z * k2.z + q.w * k2.w;
        float p3 = q.x * k3.x + q.y * k3.y + q.z * k3.z + q.w * k3.w;
#pragma unroll
        for (int m = 1; m <= 4; m <<= 1) {
            p0 += __shfl_xor_sync(0xffffffffu, p0, m);
            p1 += __shfl_xor_sync(0xffffffffu, p1, m);
            p2 += __shfl_xor_sync(0xffffffffu, p2, m);
            p3 += __shfl_xor_sync(0xffffffffu, p3, m);
        }
        p0 = fminf(fmaxf(p0, -10.f), 10.f);
        p1 = fminf(fmaxf(p1, -10.f), 10.f);
        p2 = fminf(fmaxf(p2, -10.f), 10.f);
        p3 = fminf(fmaxf(p3, -10.f), 10.f);
        float e0 = __expf(p0);
        float e1 = __expf(p1);
        float e2 = __expf(p2);
        float e3 = __expf(p3);
        denom += (e0 + e1) + (e2 + e3);
        ax = fmaf(e0, v0.x, ax); ax = fmaf(e1, v1.x, ax);
        ax = fmaf(e2, v2.x, ax); ax = fmaf(e3, v3.x, ax);
        ay = fmaf(e0, v0.y, ay); ay = fmaf(e1, v1.y, ay);
        ay = fmaf(e2, v2.y, ay); ay = fmaf(e3, v3.y, ay);
        az = fmaf(e0, v0.z, az); az = fmaf(e1, v1.z, az);
        az = fmaf(e2, v2.z, az); az = fmaf(e3, v3.z, az);
        aw = fmaf(e0, v0.w, aw); aw = fmaf(e1, v1.w, aw);
        aw = fmaf(e2, v2.w, aw); aw = fmaf(e3, v3.w, aw);
    }
    for (; i < end; i++) {
        int c = __ldg(g_adj + i);
        const float4 k4 = __ldg((const float4*)(g_K + (size_t)c * LATDIM) + lane);
        const float4 v4 = __ldg((const float4*)(g_V + (size_t)c * LATDIM) + lane);
        float p = q.x * k4.x + q.y * k4.y + q.z * k4.z + q.w * k4.w;
        p += __shfl_xor_sync(0xffffffffu, p, 1);
        p += __shfl_xor_sync(0xffffffffu, p, 2);
        p += __shfl_xor_sync(0xffffffffu, p, 4);
        p = fminf(fmaxf(p, -10.f), 10.f);
        float e = __expf(p);
        denom += e;
        ax = fmaf(e, v4.x, ax);
        ay = fmaf(e, v4.y, ay);
        az = fmaf(e, v4.z, az);
        aw = fmaf(e, v4.w, aw);
    }

    float inv = 1.f / (denom + 1e-8f);
    float4 o = make_float4(ax * inv, ay * inv, az * inv, aw * inv);
    *((float4*)out + (size_t)warp * 32 + lane) = o;
}

// ============================================================
extern "C" void kernel_launch(void* const* d_in, const int* in_sizes, int n_in,
                              void* d_out, int out_size) {
    const float* E    = (const float*)d_in[0];
    const float* qW   = (const float*)d_in[1];
    const float* kW   = (const float*)d_in[2];
    const float* vW   = (const float*)d_in[3];
    const int*   rows = (const int*)d_in[4];
    const int*   cols = (const int*)d_in[5];

    int N  = in_sizes[0] / LATDIM;
    int Eg = in_sizes[4];

    int nb = (N + 1023) / 1024;   // 49 blocks — all co-resident

    dim3 gg((N + 127) / 128, 4);
    gemm3_hist_kernel<<<gg, 256>>>(E, qW, kW, vW, rows, N, Eg);   // 1
    scan_fused<<<nb, 1024>>>(N);                                  // 2
    scatter_kernel<<<(Eg + 255) / 256, 256>>>(rows, cols, Eg);    // 3
    attn_kernel<<<(N + 7) / 8, 256>>>((float*)d_out, N);          // 4 <- ncu slot
}